// round 3
// baseline (speedup 1.0000x reference)
#include <cuda_runtime.h>

// YOLO loss, fused single-pass.
// predictions: (B=4096, S=7, S=7, NB=2, 85) fp32
// targets_boxes: (B, 20, 4) fp32 ; targets_labels: (B, 20) int32
// out: scalar fp32

#define S_GRID 7
#define NB 2
#define NC 80
#define NBOX 20
#define CELLS (S_GRID * S_GRID)
#define ROW 85            // 5 + NC
#define WARPS_PER_BLOCK 8
#define FULLMASK 0xffffffffu

__global__ void yl_init_out(float* out) { *out = 0.0f; }

__global__ __launch_bounds__(WARPS_PER_BLOCK * 32)
void yl_main(const float* __restrict__ pred,
             const float* __restrict__ boxes,
             const int*   __restrict__ labels,
             float* __restrict__ out,
             int total_cells, float inv_B)
{
    const int lane = threadIdx.x & 31;
    const int wib  = threadIdx.x >> 5;
    const int cell_g = blockIdx.x * WARPS_PER_BLOCK + wib;

    float acc = 0.0f;

    if (cell_g < total_cells) {
        const int b    = cell_g / CELLS;
        const int cidx = cell_g - b * CELLS;
        const int ci   = cidx / S_GRID;      // row index i (y)
        const int cj   = cidx - ci * S_GRID; // col index j (x)

        // ---- target encoding: lanes 0..19 each own one box ----
        float tx = 0.f, ty = 0.f, tw = 0.f, th = 0.f;
        int   mylbl = 0;
        int   match = 0;
        if (lane < NBOX) {
            const float4 bb = *reinterpret_cast<const float4*>(
                boxes + ((size_t)b * NBOX + lane) * 4);
            float x = (bb.x + bb.z) * 0.5f;
            float y = (bb.y + bb.w) * 0.5f;
            tw = bb.z - bb.x;
            th = bb.w - bb.y;
            int jb = (int)floorf(x * (float)S_GRID);
            jb = min(max(jb, 0), S_GRID - 1);
            int ib = (int)floorf(y * (float)S_GRID);
            ib = min(max(ib, 0), S_GRID - 1);
            tx = x * (float)S_GRID - (float)jb;
            ty = y * (float)S_GRID - (float)ib;
            match = (jb == cj) && (ib == ci);
            mylbl = labels[(size_t)b * NBOX + lane];
        }
        const unsigned mmask = __ballot_sync(FULLMASK, match);

        const float* prow = pred + (size_t)cell_g * (NB * ROW);

        if (mmask == 0u) {
            // ---- no-object cell: only pconf of each box ----
            if (lane < NB) {
                float pc = __ldcs(prow + lane * ROW + 4);
                acc = 0.5f * pc * pc;   // LAMBDA_NOOBJ = 0.5
            }
        } else {
            // winner = lowest box index mapping to this cell
            const int wlane = __ffs(mmask) - 1;
            tx = __shfl_sync(FULLMASK, tx, wlane);
            ty = __shfl_sync(FULLMASK, ty, wlane);
            tw = __shfl_sync(FULLMASK, tw, wlane);
            th = __shfl_sync(FULLMASK, th, wlane);
            const int lbl = __shfl_sync(FULLMASK, mylbl, wlane);

            // ---- IoU for both predictor boxes (lanes 0,1) ----
            float iou = 0.f, px = 0.f, py = 0.f, pw = 0.f, ph = 0.f, pc = 0.f;
            if (lane < NB) {
                const float* r = prow + lane * ROW;
                px = __ldcs(r + 0); py = __ldcs(r + 1);
                pw = __ldcs(r + 2); ph = __ldcs(r + 3);
                pc = __ldcs(r + 4);
                // exact reference arithmetic ordering
                float ax1 = px - pw * 0.5f, ay1 = py - ph * 0.5f;
                float ax2 = px + pw * 0.5f, ay2 = py + ph * 0.5f;
                float bx1 = tx - tw * 0.5f, by1 = ty - th * 0.5f;
                float bx2 = tx + tw * 0.5f, by2 = ty + th * 0.5f;
                float iw = fminf(ax2, bx2) - fmaxf(ax1, bx1);
                iw = fmaxf(iw, 0.0f);
                float ih = fminf(ay2, by2) - fmaxf(ay1, by1);
                ih = fmaxf(ih, 0.0f);
                float inter = iw * ih;
                float uni = (ax2 - ax1) * (ay2 - ay1)
                          + (bx2 - bx1) * (by2 - by1) - inter;
                iou = inter / (uni + 1e-6f);
            }
            const float iou0 = __shfl_sync(FULLMASK, iou, 0);
            const float iou1 = __shfl_sync(FULLMASK, iou, 1);
            // jnp.argmax: first max wins -> box1 only if strictly greater
            const int best = (iou1 > iou0) ? 1 : 0;

            if (lane == best) {
                float dx = px - tx, dy = py - ty;
                acc += 5.0f * (dx * dx + dy * dy);                 // LAMBDA_COORD
                float sw = sqrtf(fmaxf(pw, 1e-6f)) - sqrtf(fmaxf(tw, 1e-6f));
                float sh = sqrtf(fmaxf(ph, 1e-6f)) - sqrtf(fmaxf(th, 1e-6f));
                acc += 5.0f * (sw * sw + sh * sh);
                float dc = pc - 1.0f;                               // tconf = 1
                acc += dc * dc;
            }

            // ---- class loss over responsible box, 32 lanes stride 80 cols ----
            const float* cls = prow + best * ROW + 5;
            #pragma unroll
            for (int c = lane; c < NC; c += 32) {
                float d = __ldcs(cls + c) - ((c == lbl) ? 1.0f : 0.0f);
                acc += d * d;
            }
        }
    }

    // ---- warp reduce ----
    #pragma unroll
    for (int off = 16; off > 0; off >>= 1)
        acc += __shfl_down_sync(FULLMASK, acc, off);

    // ---- block reduce ----
    __shared__ float wsum[WARPS_PER_BLOCK];
    if (lane == 0) wsum[wib] = acc;
    __syncthreads();
    if (wib == 0) {
        float s = (lane < WARPS_PER_BLOCK) ? wsum[lane] : 0.0f;
        #pragma unroll
        for (int off = 4; off > 0; off >>= 1)
            s += __shfl_down_sync(FULLMASK, s, off);
        if (lane == 0)
            atomicAdd(out, s * inv_B);
    }
}

extern "C" void kernel_launch(void* const* d_in, const int* in_sizes, int n_in,
                              void* d_out, int out_size)
{
    const float* pred   = (const float*)d_in[0];
    const float* boxes  = (const float*)d_in[1];
    const int*   labels = (const int*)d_in[2];
    float* out = (float*)d_out;

    // B from predictions element count: B * 7*7*2*85
    const int B = in_sizes[0] / (CELLS * NB * ROW);
    const int total_cells = B * CELLS;
    const float inv_B = 1.0f / (float)B;

    yl_init_out<<<1, 1>>>(out);

    const int blocks = (total_cells + WARPS_PER_BLOCK - 1) / WARPS_PER_BLOCK;
    yl_main<<<blocks, WARPS_PER_BLOCK * 32>>>(pred, boxes, labels, out,
                                              total_cells, inv_B);
}

// round 4
// speedup vs baseline: 1.4411x; 1.4411x over previous
#include <cuda_runtime.h>

// YOLO loss — one block per batch image, shared-memory target table.
// predictions: (B=4096, 7, 7, 2, 85) fp32
// targets_boxes: (B, 20, 4) fp32 ; targets_labels: (B, 20) int32
// out: scalar fp32

#define S_GRID 7
#define NB 2
#define NC 80
#define NBOX 20
#define CELLS (S_GRID * S_GRID)
#define ROW 85
#define THREADS 256
#define NWARPS (THREADS / 32)
#define FULLMASK 0xffffffffu

__global__ void yl_init_out(float* out) { *out = 0.0f; }

__global__ __launch_bounds__(THREADS)
void yl_main(const float* __restrict__ pred,
             const float* __restrict__ boxes,
             const int*   __restrict__ labels,
             float* __restrict__ out,
             float inv_B)
{
    const int b    = blockIdx.x;
    const int tid  = threadIdx.x;
    const int lane = tid & 31;
    const int wib  = tid >> 5;

    __shared__ int   win[CELLS];            // winner box index per cell (NBOX = none)
    __shared__ float btx[NBOX], bty[NBOX], btw[NBOX], bth[NBOX];
    __shared__ int   blb[NBOX];
    __shared__ float wsum[NWARPS];

    if (tid < CELLS) win[tid] = NBOX;
    __syncthreads();

    // ---- encode targets once per image (20 threads) ----
    if (tid < NBOX) {
        const float4 bb = *reinterpret_cast<const float4*>(
            boxes + ((size_t)b * NBOX + tid) * 4);
        float x = (bb.x + bb.z) * 0.5f;
        float y = (bb.y + bb.w) * 0.5f;
        btw[tid] = bb.z - bb.x;
        bth[tid] = bb.w - bb.y;
        int jb = min(max((int)floorf(x * (float)S_GRID), 0), S_GRID - 1);
        int ib = min(max((int)floorf(y * (float)S_GRID), 0), S_GRID - 1);
        btx[tid] = x * (float)S_GRID - (float)jb;
        bty[tid] = y * (float)S_GRID - (float)ib;
        blb[tid] = labels[(size_t)b * NBOX + tid];
        atomicMin(&win[ib * S_GRID + jb], tid);   // min box index wins
    }
    __syncthreads();

    float acc = 0.0f;
    const float* pbase = pred + (size_t)b * (CELLS * NB * ROW);

    // ---- Pass A: no-object confidence, one thread per (cell, box) ----
    if (tid < CELLS * NB) {
        const int c  = tid >> 1;
        const int bx = tid & 1;
        if (win[c] >= NBOX) {
            float pc = __ldcs(pbase + c * (NB * ROW) + bx * ROW + 4);
            acc += 0.5f * pc * pc;              // LAMBDA_NOOBJ
        }
    }

    // ---- Pass B: object cells, one warp per cell (strided) ----
    for (int c = wib; c < CELLS; c += NWARPS) {
        const int w = win[c];                   // warp-uniform
        if (w >= NBOX) continue;

        const float tx = btx[w], ty = bty[w], tw = btw[w], th = bth[w];
        const int   lbl = blb[w];
        const float* prow = pbase + c * (NB * ROW);

        float iou = 0.f, px = 0.f, py = 0.f, pw = 0.f, ph = 0.f, pc = 0.f;
        if (lane < NB) {
            const float* r = prow + lane * ROW;
            px = __ldcs(r + 0); py = __ldcs(r + 1);
            pw = __ldcs(r + 2); ph = __ldcs(r + 3);
            pc = __ldcs(r + 4);
            // exact reference arithmetic ordering
            float ax1 = px - pw * 0.5f, ay1 = py - ph * 0.5f;
            float ax2 = px + pw * 0.5f, ay2 = py + ph * 0.5f;
            float bx1 = tx - tw * 0.5f, by1 = ty - th * 0.5f;
            float bx2 = tx + tw * 0.5f, by2 = ty + th * 0.5f;
            float iw = fmaxf(fminf(ax2, bx2) - fmaxf(ax1, bx1), 0.0f);
            float ih = fmaxf(fminf(ay2, by2) - fmaxf(ay1, by1), 0.0f);
            float inter = iw * ih;
            float uni = (ax2 - ax1) * (ay2 - ay1)
                      + (bx2 - bx1) * (by2 - by1) - inter;
            iou = inter / (uni + 1e-6f);
        }
        const float iou0 = __shfl_sync(FULLMASK, iou, 0);
        const float iou1 = __shfl_sync(FULLMASK, iou, 1);
        const int best = (iou1 > iou0) ? 1 : 0;  // jnp.argmax: first max wins

        if (lane == best) {
            float dx = px - tx, dy = py - ty;
            acc += 5.0f * (dx * dx + dy * dy);              // LAMBDA_COORD * xy
            float sw = sqrtf(fmaxf(pw, 1e-6f)) - sqrtf(fmaxf(tw, 1e-6f));
            float sh = sqrtf(fmaxf(ph, 1e-6f)) - sqrtf(fmaxf(th, 1e-6f));
            acc += 5.0f * (sw * sw + sh * sh);              // LAMBDA_COORD * wh
            float dc = pc - 1.0f;                           // tconf = 1
            acc += dc * dc;                                 // conf_obj
        }

        // class loss for responsible box: 32 lanes stride 80 columns
        const float* cls = prow + best * ROW + 5;
        #pragma unroll
        for (int cc = lane; cc < NC; cc += 32) {
            float d = __ldcs(cls + cc) - ((cc == lbl) ? 1.0f : 0.0f);
            acc += d * d;
        }
    }

    // ---- reduction: warp, then block, then one atomic per block ----
    #pragma unroll
    for (int off = 16; off > 0; off >>= 1)
        acc += __shfl_down_sync(FULLMASK, acc, off);
    if (lane == 0) wsum[wib] = acc;
    __syncthreads();
    if (wib == 0) {
        float s = (lane < NWARPS) ? wsum[lane] : 0.0f;
        #pragma unroll
        for (int off = NWARPS / 2; off > 0; off >>= 1)
            s += __shfl_down_sync(FULLMASK, s, off);
        if (lane == 0)
            atomicAdd(out, s * inv_B);
    }
}

extern "C" void kernel_launch(void* const* d_in, const int* in_sizes, int n_in,
                              void* d_out, int out_size)
{
    const float* pred   = (const float*)d_in[0];
    const float* boxes  = (const float*)d_in[1];
    const int*   labels = (const int*)d_in[2];
    float* out = (float*)d_out;

    const int B = in_sizes[0] / (CELLS * NB * ROW);
    const float inv_B = 1.0f / (float)B;

    yl_init_out<<<1, 1>>>(out);
    yl_main<<<B, THREADS>>>(pred, boxes, labels, out, inv_B);
}

// round 5
// speedup vs baseline: 1.4543x; 1.0091x over previous
#include <cuda_runtime.h>

// YOLO loss — one block per image; thread-parallel obj-cell phases.
// predictions: (B=4096, 7, 7, 2, 85) fp32
// targets_boxes: (B, 20, 4) fp32 ; targets_labels: (B, 20) int32
// out: scalar fp32

#define S_GRID 7
#define NB 2
#define NC 80
#define NBOX 20
#define CELLS (S_GRID * S_GRID)
#define ROW 85
#define THREADS 256
#define NWARPS (THREADS / 32)
#define FULLMASK 0xffffffffu

__global__ void yl_init_out(float* out) { *out = 0.0f; }

__global__ __launch_bounds__(THREADS)
void yl_main(const float* __restrict__ pred,
             const float* __restrict__ boxes,
             const int*   __restrict__ labels,
             float* __restrict__ out,
             float inv_B)
{
    const int b    = blockIdx.x;
    const int tid  = threadIdx.x;
    const int lane = tid & 31;
    const int wib  = tid >> 5;

    __shared__ int   win[CELLS];             // winner box index per cell (NBOX = none)
    __shared__ float btx[NBOX], bty[NBOX], btw[NBOX], bth[NBOX];
    __shared__ int   blb[NBOX];
    __shared__ int   objlist[CELLS];         // compact list of obj cells
    __shared__ int   sbest[CELLS];           // responsible box per obj cell
    __shared__ int   objcnt;
    __shared__ float wsum[NWARPS];

    if (tid < CELLS) win[tid] = NBOX;
    if (tid == 0) objcnt = 0;
    __syncthreads();

    // ---- encode targets once per image (20 threads) ----
    if (tid < NBOX) {
        const float4 bb = *reinterpret_cast<const float4*>(
            boxes + ((size_t)b * NBOX + tid) * 4);
        float x = (bb.x + bb.z) * 0.5f;
        float y = (bb.y + bb.w) * 0.5f;
        btw[tid] = bb.z - bb.x;
        bth[tid] = bb.w - bb.y;
        int jb = min(max((int)floorf(x * (float)S_GRID), 0), S_GRID - 1);
        int ib = min(max((int)floorf(y * (float)S_GRID), 0), S_GRID - 1);
        btx[tid] = x * (float)S_GRID - (float)jb;
        bty[tid] = y * (float)S_GRID - (float)ib;
        blb[tid] = labels[(size_t)b * NBOX + tid];
        atomicMin(&win[ib * S_GRID + jb], tid);   // min box index wins
    }
    __syncthreads();

    float acc = 0.0f;
    const float* pbase = pred + (size_t)b * (CELLS * NB * ROW);

    // ---- Pass A: no-object confidence, one thread per (cell, box) ----
    if (tid < CELLS * NB) {
        const int c  = tid >> 1;
        const int bx = tid & 1;
        if (win[c] >= NBOX) {
            float pc = __ldcs(pbase + c * (NB * ROW) + bx * ROW + 4);
            acc += 0.5f * pc * pc;               // LAMBDA_NOOBJ
        }
    }

    // ---- Pass B1: one thread per obj cell — IoU both boxes, coord/conf loss ----
    if (tid < CELLS) {
        const int c = tid;
        const int w = win[c];
        if (w < NBOX) {
            const float tx = btx[w], ty = bty[w], tw = btw[w], th = bth[w];
            const float* prow = pbase + c * (NB * ROW);

            // load both boxes' 5 floats up front (10 independent loads)
            float p0[5], p1[5];
            #pragma unroll
            for (int k = 0; k < 5; k++) p0[k] = __ldcs(prow + k);
            #pragma unroll
            for (int k = 0; k < 5; k++) p1[k] = __ldcs(prow + ROW + k);

            const float bx1 = tx - tw * 0.5f, by1 = ty - th * 0.5f;
            const float bx2 = tx + tw * 0.5f, by2 = ty + th * 0.5f;
            const float barea = (bx2 - bx1) * (by2 - by1);

            float iou[2];
            #pragma unroll
            for (int bxi = 0; bxi < 2; bxi++) {
                const float* p = bxi ? p1 : p0;
                float ax1 = p[0] - p[2] * 0.5f, ay1 = p[1] - p[3] * 0.5f;
                float ax2 = p[0] + p[2] * 0.5f, ay2 = p[1] + p[3] * 0.5f;
                float iw = fmaxf(fminf(ax2, bx2) - fmaxf(ax1, bx1), 0.0f);
                float ih = fmaxf(fminf(ay2, by2) - fmaxf(ay1, by1), 0.0f);
                float inter = iw * ih;
                float uni = (ax2 - ax1) * (ay2 - ay1) + barea - inter;
                iou[bxi] = inter / (uni + 1e-6f);
            }
            const int best = (iou[1] > iou[0]) ? 1 : 0;  // first max wins
            const float* p = best ? p1 : p0;

            float dx = p[0] - tx, dy = p[1] - ty;
            acc += 5.0f * (dx * dx + dy * dy);               // LAMBDA_COORD * xy
            float sw = sqrtf(fmaxf(p[2], 1e-6f)) - sqrtf(fmaxf(tw, 1e-6f));
            float sh = sqrtf(fmaxf(p[3], 1e-6f)) - sqrtf(fmaxf(th, 1e-6f));
            acc += 5.0f * (sw * sw + sh * sh);               // LAMBDA_COORD * wh
            float dc = p[4] - 1.0f;                          // tconf = 1
            acc += dc * dc;                                  // conf_obj

            sbest[c] = best;
            int slot = atomicAdd(&objcnt, 1);
            objlist[slot] = c;
        }
    }
    __syncthreads();

    // ---- Pass B2: class loss, flat over (obj cell, class) across block ----
    const int total = objcnt * NC;
    for (int k = tid; k < total; k += THREADS) {
        const int oc  = k / NC;           // mul-shift
        const int cc  = k - oc * NC;
        const int c   = objlist[oc];
        const int lbl = blb[win[c]];
        const float* cls = pbase + c * (NB * ROW) + sbest[c] * ROW + 5;
        float d = __ldcs(cls + cc) - ((cc == lbl) ? 1.0f : 0.0f);
        acc += d * d;
    }

    // ---- reduction: warp, then block, then one atomic per block ----
    #pragma unroll
    for (int off = 16; off > 0; off >>= 1)
        acc += __shfl_down_sync(FULLMASK, acc, off);
    if (lane == 0) wsum[wib] = acc;
    __syncthreads();
    if (wib == 0) {
        float s = (lane < NWARPS) ? wsum[lane] : 0.0f;
        #pragma unroll
        for (int off = NWARPS / 2; off > 0; off >>= 1)
            s += __shfl_down_sync(FULLMASK, s, off);
        if (lane == 0)
            atomicAdd(out, s * inv_B);
    }
}

extern "C" void kernel_launch(void* const* d_in, const int* in_sizes, int n_in,
                              void* d_out, int out_size)
{
    const float* pred   = (const float*)d_in[0];
    const float* boxes  = (const float*)d_in[1];
    const int*   labels = (const int*)d_in[2];
    float* out = (float*)d_out;

    const int B = in_sizes[0] / (CELLS * NB * ROW);
    const float inv_B = 1.0f / (float)B;

    yl_init_out<<<1, 1>>>(out);
    yl_main<<<B, THREADS>>>(pred, boxes, labels, out, inv_B);
}

// round 6
// speedup vs baseline: 1.8276x; 1.2567x over previous
#include <cuda_runtime.h>

// YOLO loss — flat barrier-free multi-kernel pipeline.
// predictions: (B<=4096, 7, 7, 2, 85) fp32
// targets_boxes: (B, 20, 4) fp32 ; targets_labels: (B, 20) int32
// out: scalar fp32

#define S_GRID 7
#define NB 2
#define NC 80
#define NBOX 20
#define CELLS (S_GRID * S_GRID)
#define ROW 85
#define THREADS 256
#define NWARPS (THREADS / 32)
#define FULLMASK 0xffffffffu
#define MAX_B 4096

__device__ int  g_win[MAX_B * CELLS];     // winner box index per cell (NBOX = none)
__device__ int2 g_list[MAX_B * CELLS];    // (pred float offset of class block, label)
__device__ int  g_cnt;

// ---------------- init ----------------
__global__ __launch_bounds__(THREADS)
void k_init(float* out, int total_cells)
{
    int i = blockIdx.x * THREADS + threadIdx.x;
    if (i < total_cells) g_win[i] = NBOX;
    if (i == 0) { g_cnt = 0; *out = 0.0f; }
}

// ---------------- encode: one thread per (image, box) ----------------
__global__ __launch_bounds__(THREADS)
void k_encode(const float* __restrict__ boxes, int total_tb)
{
    int i = blockIdx.x * THREADS + threadIdx.x;
    if (i >= total_tb) return;
    const int b  = i / NBOX;
    const int n  = i - b * NBOX;
    const float4 bb = *reinterpret_cast<const float4*>(boxes + (size_t)i * 4);
    float x = (bb.x + bb.z) * 0.5f;
    float y = (bb.y + bb.w) * 0.5f;
    int jb = min(max((int)floorf(x * (float)S_GRID), 0), S_GRID - 1);
    int ib = min(max((int)floorf(y * (float)S_GRID), 0), S_GRID - 1);
    atomicMin(&g_win[b * CELLS + ib * S_GRID + jb], n);
}

// ---------------- per-cell losses + worklist compaction ----------------
__global__ __launch_bounds__(THREADS)
void k_cell(const float* __restrict__ pred,
            const float* __restrict__ boxes,
            const int*   __restrict__ labels,
            float* __restrict__ out,
            int total_cells, float inv_B)
{
    const int tid  = threadIdx.x;
    const int lane = tid & 31;
    const int wib  = tid >> 5;
    const int cg   = blockIdx.x * THREADS + tid;

    float acc = 0.0f;
    bool  isobj = false;
    int   offset = 0, lbl = 0;

    if (cg < total_cells) {
        const int w = g_win[cg];
        const float* prow = pred + (size_t)cg * (NB * ROW);

        if (w >= NBOX) {
            // no-object: both boxes' confidence only
            float c0 = __ldcs(prow + 4);
            float c1 = __ldcs(prow + ROW + 4);
            acc = 0.5f * (c0 * c0 + c1 * c1);          // LAMBDA_NOOBJ
        } else {
            const int b    = cg / CELLS;
            const int cidx = cg - b * CELLS;
            const int ci   = cidx / S_GRID;
            const int cj   = cidx - ci * S_GRID;

            // recompute target from winning box (its clipped cell == this cell)
            const float4 bb = *reinterpret_cast<const float4*>(
                boxes + ((size_t)b * NBOX + w) * 4);
            const float x  = (bb.x + bb.z) * 0.5f;
            const float y  = (bb.y + bb.w) * 0.5f;
            const float tw = bb.z - bb.x;
            const float th = bb.w - bb.y;
            const float tx = x * (float)S_GRID - (float)cj;
            const float ty = y * (float)S_GRID - (float)ci;

            // 10 independent loads up front
            float p0[5], p1[5];
            #pragma unroll
            for (int k = 0; k < 5; k++) p0[k] = __ldcs(prow + k);
            #pragma unroll
            for (int k = 0; k < 5; k++) p1[k] = __ldcs(prow + ROW + k);

            const float bx1 = tx - tw * 0.5f, by1 = ty - th * 0.5f;
            const float bx2 = tx + tw * 0.5f, by2 = ty + th * 0.5f;
            const float barea = (bx2 - bx1) * (by2 - by1);

            float iou[2];
            #pragma unroll
            for (int bxi = 0; bxi < 2; bxi++) {
                const float* p = bxi ? p1 : p0;
                float ax1 = p[0] - p[2] * 0.5f, ay1 = p[1] - p[3] * 0.5f;
                float ax2 = p[0] + p[2] * 0.5f, ay2 = p[1] + p[3] * 0.5f;
                float iw = fmaxf(fminf(ax2, bx2) - fmaxf(ax1, bx1), 0.0f);
                float ih = fmaxf(fminf(ay2, by2) - fmaxf(ay1, by1), 0.0f);
                float inter = iw * ih;
                float uni = (ax2 - ax1) * (ay2 - ay1) + barea - inter;
                iou[bxi] = inter / (uni + 1e-6f);
            }
            const int best = (iou[1] > iou[0]) ? 1 : 0;   // first max wins
            const float* p = best ? p1 : p0;

            float dx = p[0] - tx, dy = p[1] - ty;
            acc += 5.0f * (dx * dx + dy * dy);                    // coord xy
            float sw = sqrtf(fmaxf(p[2], 1e-6f)) - sqrtf(fmaxf(tw, 1e-6f));
            float sh = sqrtf(fmaxf(p[3], 1e-6f)) - sqrtf(fmaxf(th, 1e-6f));
            acc += 5.0f * (sw * sw + sh * sh);                    // coord wh
            float dc = p[4] - 1.0f;
            acc += dc * dc;                                       // conf obj

            isobj  = true;
            offset = cg * (NB * ROW) + best * ROW + 5;
            lbl    = labels[(size_t)b * NBOX + w];
        }
    }

    // warp-aggregated worklist append
    const unsigned m = __ballot_sync(FULLMASK, isobj);
    if (m) {
        const int leader = __ffs(m) - 1;
        int base = 0;
        if (lane == leader) base = atomicAdd(&g_cnt, __popc(m));
        base = __shfl_sync(FULLMASK, base, leader);
        if (isobj) {
            const int pos = base + __popc(m & ((1u << lane) - 1u));
            g_list[pos] = make_int2(offset, lbl);
        }
    }

    // block reduce + one atomic
    #pragma unroll
    for (int off = 16; off > 0; off >>= 1)
        acc += __shfl_down_sync(FULLMASK, acc, off);
    __shared__ float wsum[NWARPS];
    if (lane == 0) wsum[wib] = acc;
    __syncthreads();
    if (wib == 0) {
        float s = (lane < NWARPS) ? wsum[lane] : 0.0f;
        #pragma unroll
        for (int off = NWARPS / 2; off > 0; off >>= 1)
            s += __shfl_down_sync(FULLMASK, s, off);
        if (lane == 0) atomicAdd(out, s * inv_B);
    }
}

// ---------------- class loss over compacted obj cells ----------------
__global__ __launch_bounds__(THREADS)
void k_cls(const float* __restrict__ pred,
           float* __restrict__ out,
           float inv_B)
{
    const int tid  = threadIdx.x;
    const int lane = tid & 31;
    const int wib  = tid >> 5;

    const int total = g_cnt * NC;
    float acc = 0.0f;

    for (int k = blockIdx.x * THREADS + tid; k < total;
         k += gridDim.x * THREADS) {
        const int oc = k / NC;
        const int cc = k - oc * NC;
        const int2 e = g_list[oc];
        float d = __ldcs(pred + e.x + cc) - ((cc == e.y) ? 1.0f : 0.0f);
        acc += d * d;
    }

    #pragma unroll
    for (int off = 16; off > 0; off >>= 1)
        acc += __shfl_down_sync(FULLMASK, acc, off);
    __shared__ float wsum[NWARPS];
    if (lane == 0) wsum[wib] = acc;
    __syncthreads();
    if (wib == 0) {
        float s = (lane < NWARPS) ? wsum[lane] : 0.0f;
        #pragma unroll
        for (int off = NWARPS / 2; off > 0; off >>= 1)
            s += __shfl_down_sync(FULLMASK, s, off);
        if (lane == 0) atomicAdd(out, s * inv_B);
    }
}

extern "C" void kernel_launch(void* const* d_in, const int* in_sizes, int n_in,
                              void* d_out, int out_size)
{
    const float* pred   = (const float*)d_in[0];
    const float* boxes  = (const float*)d_in[1];
    const int*   labels = (const int*)d_in[2];
    float* out = (float*)d_out;

    const int B = in_sizes[0] / (CELLS * NB * ROW);
    const int total_cells = B * CELLS;
    const int total_tb    = B * NBOX;
    const float inv_B = 1.0f / (float)B;

    const int gb_cells = (total_cells + THREADS - 1) / THREADS;
    const int gb_tb    = (total_tb + THREADS - 1) / THREADS;

    k_init  <<<gb_cells, THREADS>>>(out, total_cells);
    k_encode<<<gb_tb,    THREADS>>>(boxes, total_tb);
    k_cell  <<<gb_cells, THREADS>>>(pred, boxes, labels, out,
                                    total_cells, inv_B);
    k_cls   <<<2048,     THREADS>>>(pred, out, inv_B);
}

// round 7
// speedup vs baseline: 2.5194x; 1.3785x over previous
#include <cuda_runtime.h>

// YOLO loss — 3-kernel pipeline, class loss fused warp-cooperatively.
// predictions: (B<=4096, 7, 7, 2, 85) fp32
// targets_boxes: (B, 20, 4) fp32 ; targets_labels: (B, 20) int32
// out: scalar fp32

#define S_GRID 7
#define NB 2
#define NC 80
#define NBOX 20
#define CELLS (S_GRID * S_GRID)
#define ROW 85
#define THREADS 256
#define NWARPS (THREADS / 32)
#define FULLMASK 0xffffffffu
#define MAX_B 4096

__device__ int g_win[MAX_B * CELLS];   // winner box index per cell (NBOX = none)

// ---------------- init ----------------
__global__ __launch_bounds__(THREADS)
void k_init(float* out, int total_cells)
{
    int i = blockIdx.x * THREADS + threadIdx.x;
    if (i < total_cells) g_win[i] = NBOX;
    if (i == 0) *out = 0.0f;
}

// ---------------- encode: one thread per (image, box) ----------------
__global__ __launch_bounds__(THREADS)
void k_encode(const float* __restrict__ boxes, int total_tb)
{
    int i = blockIdx.x * THREADS + threadIdx.x;
    if (i >= total_tb) return;
    const int b = i / NBOX;
    const int n = i - b * NBOX;
    const float4 bb = *reinterpret_cast<const float4*>(boxes + (size_t)i * 4);
    float x = (bb.x + bb.z) * 0.5f;
    float y = (bb.y + bb.w) * 0.5f;
    int jb = min(max((int)floorf(x * (float)S_GRID), 0), S_GRID - 1);
    int ib = min(max((int)floorf(y * (float)S_GRID), 0), S_GRID - 1);
    atomicMin(&g_win[b * CELLS + ib * S_GRID + jb], n);
}

// ---------------- everything else: one thread per cell ----------------
__global__ __launch_bounds__(THREADS)
void k_cell(const float* __restrict__ pred,
            const float* __restrict__ boxes,
            const int*   __restrict__ labels,
            float* __restrict__ out,
            int total_cells, float inv_B)
{
    const int tid  = threadIdx.x;
    const int lane = tid & 31;
    const int wib  = tid >> 5;
    const int cg   = blockIdx.x * THREADS + tid;

    float acc = 0.0f;
    bool  isobj = false;
    int   offset = 0, lbl = 0;

    if (cg < total_cells) {
        const int w = g_win[cg];
        const float* prow = pred + (size_t)cg * (NB * ROW);

        if (w >= NBOX) {
            // no-object: both boxes' confidence only
            float c0 = __ldcs(prow + 4);
            float c1 = __ldcs(prow + ROW + 4);
            acc = 0.5f * (c0 * c0 + c1 * c1);          // LAMBDA_NOOBJ
        } else {
            const int b    = cg / CELLS;
            const int cidx = cg - b * CELLS;
            const int ci   = cidx / S_GRID;
            const int cj   = cidx - ci * S_GRID;

            // recompute target from winning box (its clipped cell == this cell)
            const float4 bb = *reinterpret_cast<const float4*>(
                boxes + ((size_t)b * NBOX + w) * 4);
            const float x  = (bb.x + bb.z) * 0.5f;
            const float y  = (bb.y + bb.w) * 0.5f;
            const float tw = bb.z - bb.x;
            const float th = bb.w - bb.y;
            const float tx = x * (float)S_GRID - (float)cj;
            const float ty = y * (float)S_GRID - (float)ci;

            // 10 independent loads up front
            float p0[5], p1[5];
            #pragma unroll
            for (int k = 0; k < 5; k++) p0[k] = __ldcs(prow + k);
            #pragma unroll
            for (int k = 0; k < 5; k++) p1[k] = __ldcs(prow + ROW + k);

            const float bx1 = tx - tw * 0.5f, by1 = ty - th * 0.5f;
            const float bx2 = tx + tw * 0.5f, by2 = ty + th * 0.5f;
            const float barea = (bx2 - bx1) * (by2 - by1);

            float iou[2];
            #pragma unroll
            for (int bxi = 0; bxi < 2; bxi++) {
                const float* p = bxi ? p1 : p0;
                float ax1 = p[0] - p[2] * 0.5f, ay1 = p[1] - p[3] * 0.5f;
                float ax2 = p[0] + p[2] * 0.5f, ay2 = p[1] + p[3] * 0.5f;
                float iw = fmaxf(fminf(ax2, bx2) - fmaxf(ax1, bx1), 0.0f);
                float ih = fmaxf(fminf(ay2, by2) - fmaxf(ay1, by1), 0.0f);
                float inter = iw * ih;
                float uni = (ax2 - ax1) * (ay2 - ay1) + barea - inter;
                iou[bxi] = inter / (uni + 1e-6f);
            }
            const int best = (iou[1] > iou[0]) ? 1 : 0;   // first max wins
            const float* p = best ? p1 : p0;

            float dx = p[0] - tx, dy = p[1] - ty;
            acc += 5.0f * (dx * dx + dy * dy);                    // coord xy
            float sw = sqrtf(fmaxf(p[2], 1e-6f)) - sqrtf(fmaxf(tw, 1e-6f));
            float sh = sqrtf(fmaxf(p[3], 1e-6f)) - sqrtf(fmaxf(th, 1e-6f));
            acc += 5.0f * (sw * sw + sh * sh);                    // coord wh
            float dc = p[4] - 1.0f;
            acc += dc * dc;                                       // conf obj

            isobj  = true;
            offset = cg * (NB * ROW) + best * ROW + 5;
            lbl    = labels[(size_t)b * NBOX + w];
        }
    }

    // ---- class loss: warp-cooperative over this warp's obj cells ----
    unsigned m = __ballot_sync(FULLMASK, isobj);
    while (m) {
        const int l = __ffs(m) - 1;
        m &= m - 1;
        const int off = __shfl_sync(FULLMASK, offset, l);
        const int lb  = __shfl_sync(FULLMASK, lbl, l);
        #pragma unroll
        for (int cc = lane; cc < NC; cc += 32) {
            float d = __ldcs(pred + off + cc) - ((cc == lb) ? 1.0f : 0.0f);
            acc += d * d;
        }
    }

    // ---- block reduce + one atomic ----
    #pragma unroll
    for (int off = 16; off > 0; off >>= 1)
        acc += __shfl_down_sync(FULLMASK, acc, off);
    __shared__ float wsum[NWARPS];
    if (lane == 0) wsum[wib] = acc;
    __syncthreads();
    if (wib == 0) {
        float s = (lane < NWARPS) ? wsum[lane] : 0.0f;
        #pragma unroll
        for (int off = NWARPS / 2; off > 0; off >>= 1)
            s += __shfl_down_sync(FULLMASK, s, off);
        if (lane == 0) atomicAdd(out, s * inv_B);
    }
}

extern "C" void kernel_launch(void* const* d_in, const int* in_sizes, int n_in,
                              void* d_out, int out_size)
{
    const float* pred   = (const float*)d_in[0];
    const float* boxes  = (const float*)d_in[1];
    const int*   labels = (const int*)d_in[2];
    float* out = (float*)d_out;

    const int B = in_sizes[0] / (CELLS * NB * ROW);
    const int total_cells = B * CELLS;
    const int total_tb    = B * NBOX;
    const float inv_B = 1.0f / (float)B;

    const int gb_cells = (total_cells + THREADS - 1) / THREADS;
    const int gb_tb    = (total_tb + THREADS - 1) / THREADS;

    k_init  <<<gb_cells, THREADS>>>(out, total_cells);
    k_encode<<<gb_tb,    THREADS>>>(boxes, total_tb);
    k_cell  <<<gb_cells, THREADS>>>(pred, boxes, labels, out,
                                    total_cells, inv_B);
}

// round 9
// speedup vs baseline: 2.7361x; 1.0860x over previous
#include <cuda_runtime.h>

// YOLO loss — 2-kernel pipeline with self-resetting zero-encoded scratch.
// predictions: (B<=4096, 7, 7, 2, 85) fp32
// targets_boxes: (B, 20, 4) fp32 ; targets_labels: (B, 20) int32
// out: scalar fp32
//
// g_win encoding: 0 = no object (zero-initialized at module load, and
// restored to 0 by k_cell after each use). Otherwise value v in [1,20]
// means winner box index w = NBOX - v (atomicMax of NBOX-n == min n).

#define S_GRID 7
#define NB 2
#define NC 80
#define NBOX 20
#define CELLS (S_GRID * S_GRID)
#define ROW 85
#define THREADS 256
#define NWARPS (THREADS / 32)
#define FULLMASK 0xffffffffu
#define MAX_B 4096

__device__ int g_win[MAX_B * CELLS];   // 0 = none; else NBOX - box_index

// ---------------- encode: one thread per (image, box); also zeroes out ----
__global__ __launch_bounds__(THREADS)
void k_encode(const float* __restrict__ boxes, float* out, int total_tb)
{
    int i = blockIdx.x * THREADS + threadIdx.x;
    if (i == 0) *out = 0.0f;
    if (i >= total_tb) return;
    const int b = i / NBOX;
    const int n = i - b * NBOX;
    const float4 bb = *reinterpret_cast<const float4*>(boxes + (size_t)i * 4);
    float x = (bb.x + bb.z) * 0.5f;
    float y = (bb.y + bb.w) * 0.5f;
    int jb = min(max((int)floorf(x * (float)S_GRID), 0), S_GRID - 1);
    int ib = min(max((int)floorf(y * (float)S_GRID), 0), S_GRID - 1);
    atomicMax(&g_win[b * CELLS + ib * S_GRID + jb], NBOX - n);
}

// ---------------- everything else: one thread per cell ----------------
__global__ __launch_bounds__(THREADS)
void k_cell(const float* __restrict__ pred,
            const float* __restrict__ boxes,
            const int*   __restrict__ labels,
            float* __restrict__ out,
            int total_cells, float inv_B)
{
    const int tid  = threadIdx.x;
    const int lane = tid & 31;
    const int wib  = tid >> 5;
    const int cg   = blockIdx.x * THREADS + tid;

    float acc = 0.0f;
    bool  isobj = false;
    int   offset = 0, lbl = 0;

    if (cg < total_cells) {
        const int v = g_win[cg];
        if (v != 0) g_win[cg] = 0;           // restore zeroed invariant
        const float* prow = pred + (size_t)cg * (NB * ROW);

        if (v == 0) {
            // no-object: both boxes' confidence only
            float c0 = __ldcs(prow + 4);
            float c1 = __ldcs(prow + ROW + 4);
            acc = 0.5f * (c0 * c0 + c1 * c1);          // LAMBDA_NOOBJ
        } else {
            const int w    = NBOX - v;                 // winner box index
            const int b    = cg / CELLS;
            const int cidx = cg - b * CELLS;
            const int ci   = cidx / S_GRID;
            const int cj   = cidx - ci * S_GRID;

            // recompute target from winning box (its clipped cell == this cell)
            const float4 bb = *reinterpret_cast<const float4*>(
                boxes + ((size_t)b * NBOX + w) * 4);
            const float x  = (bb.x + bb.z) * 0.5f;
            const float y  = (bb.y + bb.w) * 0.5f;
            const float tw = bb.z - bb.x;
            const float th = bb.w - bb.y;
            const float tx = x * (float)S_GRID - (float)cj;
            const float ty = y * (float)S_GRID - (float)ci;

            // 10 independent loads up front
            float p0[5], p1[5];
            #pragma unroll
            for (int k = 0; k < 5; k++) p0[k] = __ldcs(prow + k);
            #pragma unroll
            for (int k = 0; k < 5; k++) p1[k] = __ldcs(prow + ROW + k);

            const float bx1 = tx - tw * 0.5f, by1 = ty - th * 0.5f;
            const float bx2 = tx + tw * 0.5f, by2 = ty + th * 0.5f;
            const float barea = (bx2 - bx1) * (by2 - by1);

            float iou[2];
            #pragma unroll
            for (int bxi = 0; bxi < 2; bxi++) {
                const float* p = bxi ? p1 : p0;
                float ax1 = p[0] - p[2] * 0.5f, ay1 = p[1] - p[3] * 0.5f;
                float ax2 = p[0] + p[2] * 0.5f, ay2 = p[1] + p[3] * 0.5f;
                float iw = fmaxf(fminf(ax2, bx2) - fmaxf(ax1, bx1), 0.0f);
                float ih = fmaxf(fminf(ay2, by2) - fmaxf(ay1, by1), 0.0f);
                float inter = iw * ih;
                float uni = (ax2 - ax1) * (ay2 - ay1) + barea - inter;
                iou[bxi] = inter / (uni + 1e-6f);
            }
            const int best = (iou[1] > iou[0]) ? 1 : 0;   // first max wins
            const float* p = best ? p1 : p0;

            float dx = p[0] - tx, dy = p[1] - ty;
            acc += 5.0f * (dx * dx + dy * dy);                    // coord xy
            float sw = sqrtf(fmaxf(p[2], 1e-6f)) - sqrtf(fmaxf(tw, 1e-6f));
            float sh = sqrtf(fmaxf(p[3], 1e-6f)) - sqrtf(fmaxf(th, 1e-6f));
            acc += 5.0f * (sw * sw + sh * sh);                    // coord wh
            float dc = p[4] - 1.0f;
            acc += dc * dc;                                       // conf obj

            isobj  = true;
            offset = cg * (NB * ROW) + best * ROW + 5;
            lbl    = labels[(size_t)b * NBOX + w];
        }
    }

    // ---- class loss: warp-cooperative over this warp's obj cells ----
    unsigned m = __ballot_sync(FULLMASK, isobj);
    while (m) {
        const int l = __ffs(m) - 1;
        m &= m - 1;
        const int off = __shfl_sync(FULLMASK, offset, l);
        const int lb  = __shfl_sync(FULLMASK, lbl, l);
        #pragma unroll
        for (int cc = lane; cc < NC; cc += 32) {
            float d = __ldcs(pred + off + cc) - ((cc == lb) ? 1.0f : 0.0f);
            acc += d * d;
        }
    }

    // ---- block reduce + one atomic ----
    #pragma unroll
    for (int off = 16; off > 0; off >>= 1)
        acc += __shfl_down_sync(FULLMASK, acc, off);
    __shared__ float wsum[NWARPS];
    if (lane == 0) wsum[wib] = acc;
    __syncthreads();
    if (wib == 0) {
        float s = (lane < NWARPS) ? wsum[lane] : 0.0f;
        #pragma unroll
        for (int off = NWARPS / 2; off > 0; off >>= 1)
            s += __shfl_down_sync(FULLMASK, s, off);
        if (lane == 0) atomicAdd(out, s * inv_B);
    }
}

extern "C" void kernel_launch(void* const* d_in, const int* in_sizes, int n_in,
                              void* d_out, int out_size)
{
    const float* pred   = (const float*)d_in[0];
    const float* boxes  = (const float*)d_in[1];
    const int*   labels = (const int*)d_in[2];
    float* out = (float*)d_out;

    const int B = in_sizes[0] / (CELLS * NB * ROW);
    const int total_cells = B * CELLS;
    const int total_tb    = B * NBOX;
    const float inv_B = 1.0f / (float)B;

    const int gb_cells = (total_cells + THREADS - 1) / THREADS;
    const int gb_tb    = (total_tb + THREADS - 1) / THREADS;

    k_encode<<<gb_tb,    THREADS>>>(boxes, out, total_tb);
    k_cell  <<<gb_cells, THREADS>>>(pred, boxes, labels, out,
                                    total_cells, inv_B);
}